// round 2
// baseline (speedup 1.0000x reference)
#include <cuda_runtime.h>

#define D 128
#define LAYERS 3
#define MAXN 50000
#define MAXE 1600000
#define BN_EPS 1e-5f
#define PAD 132

// ---------------- scratch (static device globals; no allocation) ----------------
__device__ int   g_counts[MAXN];
__device__ int   g_ptr[MAXN + 1];
__device__ int   g_cursor[MAXN];
__device__ int   g_csr[MAXE];
__device__ float g_h0[(size_t)MAXN * D];   // agg + self
__device__ float g_h2[(size_t)MAXN * D];   // MLP output (pre-BN)
__device__ float g_colsum[LAYERS * D];
__device__ float g_colsumsq[LAYERS * D];
__device__ float g_scale[D];
__device__ float g_shift[D];

// ---------------- zero scratch + pooled-output region ----------------
__global__ void zero_kernel(int n, float* gpool, int npool) {
    int stride = gridDim.x * blockDim.x;
    int t0 = blockIdx.x * blockDim.x + threadIdx.x;
    for (int i = t0; i < n; i += stride) g_counts[i] = 0;
    for (int i = t0; i < LAYERS * D; i += stride) { g_colsum[i] = 0.f; g_colsumsq[i] = 0.f; }
    for (int i = t0; i < npool; i += stride) gpool[i] = 0.f;
}

// ---------------- CSR build: histogram -> scan -> scatter ----------------
__global__ void hist_kernel(const int* __restrict__ dst, int e) {
    int i = blockIdx.x * blockDim.x + threadIdx.x;
    if (i < e) atomicAdd(&g_counts[dst[i]], 1);
}

__global__ void scan_kernel(int n, int chunk) {
    __shared__ int ssum[1024];
    int t = threadIdx.x;
    int lo = t * chunk;
    int hi = min(lo + chunk, n);
    int local = 0;
    for (int i = lo; i < hi; i++) local += g_counts[i];
    ssum[t] = local;
    __syncthreads();
    for (int off = 1; off < 1024; off <<= 1) {
        int v = 0;
        if (t >= off) v = ssum[t - off];
        __syncthreads();
        ssum[t] += v;
        __syncthreads();
    }
    int run = ssum[t] - local;   // exclusive prefix
    for (int i = lo; i < hi; i++) {
        g_ptr[i] = run;
        g_cursor[i] = run;
        run += g_counts[i];
    }
    if (t == 1023) g_ptr[n] = ssum[1023];
}

__global__ void scatter_kernel(const int* __restrict__ src, const int* __restrict__ dst, int e) {
    int i = blockIdx.x * blockDim.x + threadIdx.x;
    if (i < e) {
        int p = atomicAdd(&g_cursor[dst[i]], 1);
        g_csr[p] = src[i];
    }
}

// ---------------- per-node gather-sum (GIN agg + self), one warp per node ----------------
__global__ void agg_kernel(const float* __restrict__ zbase, int zstride, int n) {
    int warp = (blockIdx.x * blockDim.x + threadIdx.x) >> 5;
    int lane = threadIdx.x & 31;
    if (warp >= n) return;
    const float* zr = zbase + (size_t)warp * zstride + lane * 4;
    float4 a = *(const float4*)zr;   // self (eps = 0)
    int lo = g_ptr[warp], hi = g_ptr[warp + 1];
    for (int e = lo; e < hi; e++) {
        int s = g_csr[e];
        float4 v = __ldg((const float4*)(zbase + (size_t)s * zstride + lane * 4));
        a.x += v.x; a.y += v.y; a.z += v.z; a.w += v.w;
    }
    *(float4*)&g_h0[(size_t)warp * D + lane * 4] = a;
}

// ---------------- fused MLP: h2 = relu(h0@W1+b1)@W2+b2, + column sum/sumsq ----------------
// shared: Ws[128*128] | As[128*PAD] | Hs[128*PAD]  = (16384 + 2*128*132)*4 = 200704 bytes
#define MLP_SMEM ((16384 + 2 * 128 * PAD) * 4)

__global__ void __launch_bounds__(512, 1)
mlp_kernel(const float* __restrict__ A,
           const float* __restrict__ W1, const float* __restrict__ b1,
           const float* __restrict__ W2, const float* __restrict__ b2,
           float* __restrict__ out, int layer, int n) {
    extern __shared__ float sm[];
    float* Ws = sm;                    // 128*128
    float* As = sm + 16384;            // 128*PAD
    float* Hs = As + 128 * PAD;        // 128*PAD
    int tx = threadIdx.x;
    int row0 = blockIdx.x * 128;
    int rowsValid = min(128, n - row0);

    // load A tile (padded rows) + W1, vectorized
    for (int idx = tx; idx < 4096; idx += 512) {
        int r = idx >> 5, c4 = (idx & 31) * 4;
        float4 v = make_float4(0.f, 0.f, 0.f, 0.f);
        if (r < rowsValid) v = *(const float4*)&A[(size_t)(row0 + r) * D + c4];
        *(float4*)&As[r * PAD + c4] = v;
        *(float4*)&Ws[idx * 4] = *(const float4*)&W1[idx * 4];
    }
    __syncthreads();

    int rg = tx >> 4;   // 0..31 : row group (4 rows each)
    int cq = tx & 15;   // 0..15 : column group (8 contiguous cols: cq*8..cq*8+7)
    int cbase = cq * 8;

    float acc[4][8];
    {
        float4 bA = __ldg((const float4*)&b1[cbase]);
        float4 bB = __ldg((const float4*)&b1[cbase + 4]);
#pragma unroll
        for (int i = 0; i < 4; i++) {
            acc[i][0] = bA.x; acc[i][1] = bA.y; acc[i][2] = bA.z; acc[i][3] = bA.w;
            acc[i][4] = bB.x; acc[i][5] = bB.y; acc[i][6] = bB.z; acc[i][7] = bB.w;
        }
    }

    for (int k = 0; k < 128; k++) {
        float4 w0 = *(const float4*)&Ws[k * 128 + cbase];
        float4 w4 = *(const float4*)&Ws[k * 128 + cbase + 4];
#pragma unroll
        for (int i = 0; i < 4; i++) {
            float a = As[(rg * 4 + i) * PAD + k];
            acc[i][0] = fmaf(a, w0.x, acc[i][0]);
            acc[i][1] = fmaf(a, w0.y, acc[i][1]);
            acc[i][2] = fmaf(a, w0.z, acc[i][2]);
            acc[i][3] = fmaf(a, w0.w, acc[i][3]);
            acc[i][4] = fmaf(a, w4.x, acc[i][4]);
            acc[i][5] = fmaf(a, w4.y, acc[i][5]);
            acc[i][6] = fmaf(a, w4.z, acc[i][6]);
            acc[i][7] = fmaf(a, w4.w, acc[i][7]);
        }
    }
#pragma unroll
    for (int i = 0; i < 4; i++) {
        float4 h0v = make_float4(fmaxf(acc[i][0], 0.f), fmaxf(acc[i][1], 0.f),
                                 fmaxf(acc[i][2], 0.f), fmaxf(acc[i][3], 0.f));
        float4 h1v = make_float4(fmaxf(acc[i][4], 0.f), fmaxf(acc[i][5], 0.f),
                                 fmaxf(acc[i][6], 0.f), fmaxf(acc[i][7], 0.f));
        *(float4*)&Hs[(rg * 4 + i) * PAD + cbase] = h0v;
        *(float4*)&Hs[(rg * 4 + i) * PAD + cbase + 4] = h1v;
    }
    __syncthreads();

    for (int idx = tx; idx < 4096; idx += 512)
        *(float4*)&Ws[idx * 4] = *(const float4*)&W2[idx * 4];
    __syncthreads();

    {
        float4 bA = __ldg((const float4*)&b2[cbase]);
        float4 bB = __ldg((const float4*)&b2[cbase + 4]);
#pragma unroll
        for (int i = 0; i < 4; i++) {
            acc[i][0] = bA.x; acc[i][1] = bA.y; acc[i][2] = bA.z; acc[i][3] = bA.w;
            acc[i][4] = bB.x; acc[i][5] = bB.y; acc[i][6] = bB.z; acc[i][7] = bB.w;
        }
    }

    for (int k = 0; k < 128; k++) {
        float4 w0 = *(const float4*)&Ws[k * 128 + cbase];
        float4 w4 = *(const float4*)&Ws[k * 128 + cbase + 4];
#pragma unroll
        for (int i = 0; i < 4; i++) {
            float a = Hs[(rg * 4 + i) * PAD + k];
            acc[i][0] = fmaf(a, w0.x, acc[i][0]);
            acc[i][1] = fmaf(a, w0.y, acc[i][1]);
            acc[i][2] = fmaf(a, w0.z, acc[i][2]);
            acc[i][3] = fmaf(a, w0.w, acc[i][3]);
            acc[i][4] = fmaf(a, w4.x, acc[i][4]);
            acc[i][5] = fmaf(a, w4.y, acc[i][5]);
            acc[i][6] = fmaf(a, w4.z, acc[i][6]);
            acc[i][7] = fmaf(a, w4.w, acc[i][7]);
        }
    }
    __syncthreads();
#pragma unroll
    for (int i = 0; i < 4; i++) {
        *(float4*)&As[(rg * 4 + i) * PAD + cbase] =
            make_float4(acc[i][0], acc[i][1], acc[i][2], acc[i][3]);
        *(float4*)&As[(rg * 4 + i) * PAD + cbase + 4] =
            make_float4(acc[i][4], acc[i][5], acc[i][6], acc[i][7]);
    }
    __syncthreads();

    if (tx < 128) {   // per-column partial stats over this block's valid rows
        float s = 0.f, ss = 0.f;
        for (int r = 0; r < rowsValid; r++) {
            float v = As[r * PAD + tx];
            s += v; ss += v * v;
        }
        atomicAdd(&g_colsum[layer * D + tx], s);
        atomicAdd(&g_colsumsq[layer * D + tx], ss);
    }
    for (int idx = tx; idx < rowsValid * 32; idx += 512) {
        int r = idx >> 5, c4 = (idx & 31) * 4;
        *(float4*)&out[(size_t)(row0 + r) * D + c4] = *(const float4*)&As[r * PAD + c4];
    }
}

// ---------------- finalize BN coefficients ----------------
__global__ void bnprep_kernel(int layer, const float* __restrict__ gamma,
                              const float* __restrict__ beta, float invN) {
    int c = threadIdx.x;
    float mu = g_colsum[layer * D + c] * invN;
    float var = g_colsumsq[layer * D + c] * invN - mu * mu;
    float inv = rsqrtf(var + BN_EPS);
    float sc = gamma[c] * inv;
    g_scale[c] = sc;
    g_shift[c] = beta[c] - mu * sc;
}

// ---------------- normalize (+relu) -> z_cat slice, and atomic pool -> g_cat slice ----------------
__global__ void bnpool_kernel(const float* __restrict__ h2, const int* __restrict__ batch,
                              float* __restrict__ zout, float* __restrict__ gout,
                              int n, int do_relu) {
    int stride = gridDim.x * blockDim.x;
    for (int idx = blockIdx.x * blockDim.x + threadIdx.x; idx < n * 32; idx += stride) {
        int node = idx >> 5;
        int c = (idx & 31) * 4;
        float4 v = *(const float4*)&h2[(size_t)node * D + c];
        float4 sc = *(const float4*)&g_scale[c];
        float4 sh = *(const float4*)&g_shift[c];
        float y0 = v.x * sc.x + sh.x;
        float y1 = v.y * sc.y + sh.y;
        float y2 = v.z * sc.z + sh.z;
        float y3 = v.w * sc.w + sh.w;
        if (do_relu) {
            y0 = fmaxf(y0, 0.f); y1 = fmaxf(y1, 0.f);
            y2 = fmaxf(y2, 0.f); y3 = fmaxf(y3, 0.f);
        }
        float4 y4 = make_float4(y0, y1, y2, y3);
        *(float4*)&zout[(size_t)node * (3 * D) + c] = y4;
        int b = batch[node];
        float* gp = &gout[(size_t)b * (3 * D) + c];
        atomicAdd(gp + 0, y0);
        atomicAdd(gp + 1, y1);
        atomicAdd(gp + 2, y2);
        atomicAdd(gp + 3, y3);
    }
}

// ---------------- launch ----------------
extern "C" void kernel_launch(void* const* d_in, const int* in_sizes, int n_in,
                              void* d_out, int out_size) {
    const float* x     = (const float*)d_in[0];
    const int*   ei    = (const int*)d_in[1];
    const int*   batch = (const int*)d_in[2];
    const float* W1    = (const float*)d_in[3];
    const float* b1    = (const float*)d_in[4];
    const float* W2    = (const float*)d_in[5];
    const float* b2    = (const float*)d_in[6];
    const float* gamma = (const float*)d_in[7];
    const float* beta  = (const float*)d_in[8];

    int N = in_sizes[0] / D;
    int E = in_sizes[1] / 2;
    int G = out_size / (LAYERS * D) - N;

    float* out   = (float*)d_out;
    float* gpool = out + (size_t)N * LAYERS * D;   // g_cat region
    int npool = G * LAYERS * D;

    const int* src = ei;
    const int* dst = ei + E;

    cudaFuncSetAttribute(mlp_kernel, cudaFuncAttributeMaxDynamicSharedMemorySize, MLP_SMEM);

    float* h0 = nullptr; float* h2 = nullptr;
    cudaGetSymbolAddress((void**)&h0, g_h0);
    cudaGetSymbolAddress((void**)&h2, g_h2);

    // 1) zero scratch + pooled output
    zero_kernel<<<512, 256>>>(N, gpool, npool);
    // 2) CSR build
    int eb = (E + 255) / 256;
    hist_kernel<<<eb, 256>>>(dst, E);
    int chunk = (N + 1023) / 1024;
    scan_kernel<<<1, 1024>>>(N, chunk);
    scatter_kernel<<<eb, 256>>>(src, dst, E);

    int aggBlocks = (N * 32 + 255) / 256;
    int mlpBlocks = (N + 127) / 128;
    float invN = 1.0f / (float)N;

    for (int l = 0; l < LAYERS; l++) {
        const float* zbase;
        int zstride;
        if (l == 0) { zbase = x;                  zstride = D; }
        else        { zbase = out + (l - 1) * D;  zstride = 3 * D; }

        agg_kernel<<<aggBlocks, 256>>>(zbase, zstride, N);
        mlp_kernel<<<mlpBlocks, 512, MLP_SMEM>>>(h0, W1 + l * D * D, b1 + l * D,
                                                 W2 + l * D * D, b2 + l * D,
                                                 h2, l, N);
        bnprep_kernel<<<1, D>>>(l, gamma + l * D, beta + l * D, invN);
        bnpool_kernel<<<aggBlocks, 256>>>(h2, batch, out + l * D,
                                          gpool + l * D, N, (l != LAYERS - 1) ? 1 : 0);
    }
}

// round 5
// speedup vs baseline: 1.0742x; 1.0742x over previous
#include <cuda_runtime.h>
#include <cstdint>

#define D 128
#define LAYERS 3
#define MAXN 50000
#define MAXE 1600000
#define BN_EPS 1e-5f
#define SMS 132   // smem row stride (floats)

// ---------------- scratch (static device globals; no allocation) ----------------
__device__ int   g_counts[MAXN];
__device__ int   g_ptr[MAXN + 1];
__device__ int   g_cursor[MAXN];
__device__ int   g_csr[MAXE];
__device__ float g_h0[(size_t)MAXN * D];     // agg + self
__device__ float g_h2[(size_t)MAXN * D];     // MLP output (pre-BN)
__device__ float g_wimg[12 * 16384];         // per layer: W1_hi, W1_lo, W2_hi, W2_lo (transposed [n][k])
__device__ float g_colsum[LAYERS * D];
__device__ float g_colsumsq[LAYERS * D];
__device__ float g_scale[D];
__device__ float g_shift[D];

__device__ __forceinline__ uint32_t to_tf32(float x) {
    uint32_t r; asm("cvt.rna.tf32.f32 %0, %1;" : "=r"(r) : "f"(x)); return r;
}

#define MMA_TF32(d, a, b) \
    asm volatile("mma.sync.aligned.m16n8k8.row.col.f32.tf32.tf32.f32 " \
        "{%0,%1,%2,%3}, {%4,%5,%6,%7}, {%8,%9}, {%0,%1,%2,%3};" \
        : "+f"((d)[0]), "+f"((d)[1]), "+f"((d)[2]), "+f"((d)[3]) \
        : "r"((a)[0]), "r"((a)[1]), "r"((a)[2]), "r"((a)[3]), \
          "r"((b)[0]), "r"((b)[1]))

// ---------------- zero scratch + pooled-output region ----------------
__global__ void zero_kernel(int n, float* gpool, int npool) {
    int stride = gridDim.x * blockDim.x;
    int t0 = blockIdx.x * blockDim.x + threadIdx.x;
    for (int i = t0; i < n; i += stride) g_counts[i] = 0;
    for (int i = t0; i < LAYERS * D; i += stride) { g_colsum[i] = 0.f; g_colsumsq[i] = 0.f; }
    for (int i = t0; i < npool; i += stride) gpool[i] = 0.f;
}

// ---------------- CSR build: histogram -> scan -> scatter ----------------
__global__ void hist_kernel(const int* __restrict__ dst, int e) {
    int i = blockIdx.x * blockDim.x + threadIdx.x;
    if (i < e) atomicAdd(&g_counts[dst[i]], 1);
}

__global__ void scan_kernel(int n, int chunk) {
    __shared__ int ssum[1024];
    int t = threadIdx.x;
    int lo = t * chunk;
    int hi = min(lo + chunk, n);
    int local = 0;
    for (int i = lo; i < hi; i++) local += g_counts[i];
    ssum[t] = local;
    __syncthreads();
    for (int off = 1; off < 1024; off <<= 1) {
        int v = 0;
        if (t >= off) v = ssum[t - off];
        __syncthreads();
        ssum[t] += v;
        __syncthreads();
    }
    int run = ssum[t] - local;
    for (int i = lo; i < hi; i++) {
        g_ptr[i] = run;
        g_cursor[i] = run;
        run += g_counts[i];
    }
    if (t == 1023) g_ptr[n] = ssum[1023];
}

__global__ void scatter_kernel(const int* __restrict__ src, const int* __restrict__ dst, int e) {
    int i = blockIdx.x * blockDim.x + threadIdx.x;
    if (i < e) {
        int p = atomicAdd(&g_cursor[dst[i]], 1);
        g_csr[p] = src[i];
    }
}

// ---------------- pre-transpose + hi/lo tf32 split of all weights ----------------
// image index w = l*4 + j, j: 0=W1_hi 1=W1_lo 2=W2_hi 3=W2_lo ; layout Wt[n][k]
__global__ void wtrans_kernel(const float* __restrict__ W1, const float* __restrict__ W2) {
    int i = blockIdx.x * blockDim.x + threadIdx.x;
    if (i >= 12 * 16384) return;
    int w = i >> 14, e = i & 16383;
    int l = w >> 2, j = w & 3;
    const float* src = (j < 2) ? W1 : W2;
    int nn = e >> 7, k = e & 127;
    float v = src[l * 16384 + k * 128 + nn];
    float hi = __uint_as_float(to_tf32(v));
    float outv = (j & 1) ? __uint_as_float(to_tf32(v - hi)) : hi;
    g_wimg[w * 16384 + nn * 128 + k] = outv;
}

// ---------------- per-node gather-sum (GIN agg + self), one warp per node ----------------
__global__ void agg_kernel(const float* __restrict__ zbase, int zstride, int n) {
    int warp = (blockIdx.x * blockDim.x + threadIdx.x) >> 5;
    int lane = threadIdx.x & 31;
    if (warp >= n) return;
    const float* zr = zbase + (size_t)warp * zstride + lane * 4;
    float4 a = *(const float4*)zr;   // self (eps = 0)
    int lo = g_ptr[warp], hi = g_ptr[warp + 1];
    for (int e = lo; e < hi; e++) {
        int s = g_csr[e];
        float4 v = __ldg((const float4*)(zbase + (size_t)s * zstride + lane * 4));
        a.x += v.x; a.y += v.y; a.z += v.z; a.w += v.w;
    }
    *(float4*)&g_h0[(size_t)warp * D + lane * 4] = a;
}

// ---------------- fused MLP via tf32x3 mma.sync: h2 = relu(h0@W1+b1)@W2+b2 ----------------
// smem: Ah[128*SMS] | Al[128*SMS] | Bb[128*SMS]  = 3*128*132*4 = 202752 bytes
#define MLP_SMEM (3 * 128 * SMS * 4)

__global__ void __launch_bounds__(256, 1)
mlp_kernel(const float* __restrict__ A, const float* __restrict__ img,
           const float* __restrict__ b1, const float* __restrict__ b2,
           float* __restrict__ out, int n)
{
    extern __shared__ float sm[];
    float* Ah = sm;
    float* Al = Ah + 128 * SMS;
    float* Bb = Al + 128 * SMS;
    int tx = threadIdx.x;
    int wid = tx >> 5, lane = tx & 31;
    int g = lane >> 2, tig = lane & 3;
    int wr = wid & 3, wc = wid >> 2;       // 4 row-warps x 2 col-warps
    int row0 = blockIdx.x * 128;
    int rowsValid = min(128, n - row0);

    const float4* imgW1h = (const float4*)(img);
    const float4* imgW1l = (const float4*)(img + 16384);
    const float4* imgW2h = (const float4*)(img + 2 * 16384);
    const float4* imgW2l = (const float4*)(img + 3 * 16384);
    float4* Bb4base = (float4*)Bb;

    // stage A hi/lo + W1_hi
    for (int i = tx; i < 4096; i += 256) {
        int r = i >> 5, c4 = (i & 31) * 4;
        float4 v = make_float4(0.f, 0.f, 0.f, 0.f);
        if (r < rowsValid) v = *(const float4*)&A[(size_t)(row0 + r) * D + c4];
        float4 h;
        h.x = __uint_as_float(to_tf32(v.x));
        h.y = __uint_as_float(to_tf32(v.y));
        h.z = __uint_as_float(to_tf32(v.z));
        h.w = __uint_as_float(to_tf32(v.w));
        float4 l;
        l.x = __uint_as_float(to_tf32(v.x - h.x));
        l.y = __uint_as_float(to_tf32(v.y - h.y));
        l.z = __uint_as_float(to_tf32(v.z - h.z));
        l.w = __uint_as_float(to_tf32(v.w - h.w));
        *(float4*)&Ah[r * SMS + c4] = h;
        *(float4*)&Al[r * SMS + c4] = l;
        Bb4base[(i >> 5) * (SMS >> 2) + (i & 31)] = imgW1h[i];
    }
    __syncthreads();

    float acc[2][8][4];

    // ---- acc = b1 ----
#pragma unroll
    for (int nt = 0; nt < 8; nt++) {
        int c0 = wc * 64 + nt * 8 + 2 * tig;
        float bx = __ldg(&b1[c0]), by = __ldg(&b1[c0 + 1]);
#pragma unroll
        for (int mt = 0; mt < 2; mt++) {
            acc[mt][nt][0] = bx; acc[mt][nt][1] = by;
            acc[mt][nt][2] = bx; acc[mt][nt][3] = by;
        }
    }

    // ---- pass 1: (A_hi + A_lo) * W1_hi ----
#pragma unroll
    for (int ks = 0; ks < 16; ks++) {
        int k0 = ks * 8;
        uint32_t ah[2][4], al[2][4], b[8][2];
#pragma unroll
        for (int mt = 0; mt < 2; mt++) {
            int r = wr * 32 + mt * 16 + g;
            ah[mt][0] = __float_as_uint(Ah[r * SMS + k0 + tig]);
            ah[mt][1] = __float_as_uint(Ah[(r + 8) * SMS + k0 + tig]);
            ah[mt][2] = __float_as_uint(Ah[r * SMS + k0 + tig + 4]);
            ah[mt][3] = __float_as_uint(Ah[(r + 8) * SMS + k0 + tig + 4]);
            al[mt][0] = __float_as_uint(Al[r * SMS + k0 + tig]);
            al[mt][1] = __float_as_uint(Al[(r + 8) * SMS + k0 + tig]);
            al[mt][2] = __float_as_uint(Al[r * SMS + k0 + tig + 4]);
            al[mt][3] = __float_as_uint(Al[(r + 8) * SMS + k0 + tig + 4]);
        }
#pragma unroll
        for (int nt = 0; nt < 8; nt++) {
            int nn = wc * 64 + nt * 8 + g;
            b[nt][0] = __float_as_uint(Bb[nn * SMS + k0 + tig]);
            b[nt][1] = __float_as_uint(Bb[nn * SMS + k0 + tig + 4]);
        }
#pragma unroll
        for (int mt = 0; mt < 2; mt++)
#pragma unroll
            for (int nt = 0; nt < 8; nt++) {
                MMA_TF32(acc[mt][nt], ah[mt], b[nt]);
                MMA_TF32(acc[mt][nt], al[mt], b[nt]);
            }
    }
    __syncthreads();
    for (int i = tx; i < 4096; i += 256)
        Bb4base[(i >> 5) * (SMS >> 2) + (i & 31)] = imgW1l[i];
    __syncthreads();

    // ---- pass 2: A_hi * W1_lo ----
#pragma unroll
    for (int ks = 0; ks < 16; ks++) {
        int k0 = ks * 8;
        uint32_t ah[2][4], b[8][2];
#pragma unroll
        for (int mt = 0; mt < 2; mt++) {
            int r = wr * 32 + mt * 16 + g;
            ah[mt][0] = __float_as_uint(Ah[r * SMS + k0 + tig]);
            ah[mt][1] = __float_as_uint(Ah[(r + 8) * SMS + k0 + tig]);
            ah[mt][2] = __float_as_uint(Ah[r * SMS + k0 + tig + 4]);
            ah[mt][3] = __float_as_uint(Ah[(r + 8) * SMS + k0 + tig + 4]);
        }
#pragma unroll
        for (int nt = 0; nt < 8; nt++) {
            int nn = wc * 64 + nt * 8 + g;
            b[nt][0] = __float_as_uint(Bb[nn * SMS + k0 + tig]);
            b[nt][1] = __float_as_uint(Bb[nn * SMS + k0 + tig + 4]);
        }
#pragma unroll
        for (int mt = 0; mt < 2; mt++)
#pragma unroll
            for (int nt = 0; nt < 8; nt++)
                MMA_TF32(acc[mt][nt], ah[mt], b[nt]);
    }
    __syncthreads();   // all warps done reading Ah/Al/Bb

    // relu(h1), hi/lo split back into Ah/Al; stage W2_hi into Bb
#pragma unroll
    for (int mt = 0; mt < 2; mt++) {
        int r = wr * 32 + mt * 16 + g;
#pragma unroll
        for (int nt = 0; nt < 8; nt++) {
            int c0 = wc * 64 + nt * 8 + 2 * tig;
#pragma unroll
            for (int q = 0; q < 4; q++) {
                int rr = (q < 2) ? r : r + 8;
                int cc = c0 + (q & 1);
                float v = fmaxf(acc[mt][nt][q], 0.f);
                float h = __uint_as_float(to_tf32(v));
                Ah[rr * SMS + cc] = h;
                Al[rr * SMS + cc] = __uint_as_float(to_tf32(v - h));
            }
        }
    }
    for (int i = tx; i < 4096; i += 256)
        Bb4base[(i >> 5) * (SMS >> 2) + (i & 31)] = imgW2h[i];
    __syncthreads();

    // ---- acc = b2 ----
#pragma unroll
    for (int nt = 0; nt < 8; nt++) {
        int c0 = wc * 64 + nt * 8 + 2 * tig;
        float bx = __ldg(&b2[c0]), by = __ldg(&b2[c0 + 1]);
#pragma unroll
        for (int mt = 0; mt < 2; mt++) {
            acc[mt][nt][0] = bx; acc[mt][nt][1] = by;
            acc[mt][nt][2] = bx; acc[mt][nt][3] = by;
        }
    }

    // ---- pass 3: (h1_hi + h1_lo) * W2_hi ----
#pragma unroll
    for (int ks = 0; ks < 16; ks++) {
        int k0 = ks * 8;
        uint32_t ah[2][4], al[2][4], b[8][2];
#pragma unroll
        for (int mt = 0; mt < 2; mt++) {
            int r = wr * 32 + mt * 16 + g;
            ah[mt][0] = __float_as_uint(Ah[r * SMS + k0 + tig]);
            ah[mt][1] = __float_as_uint(Ah[(r + 8) * SMS + k0 + tig]);
            ah[mt][2] = __float_as_uint(Ah[r * SMS + k0 + tig + 4]);
            ah[mt][3] = __float_as_uint(Ah[(r + 8) * SMS + k0 + tig + 4]);
            al[mt][0] = __float_as_uint(Al[r * SMS + k0 + tig]);
            al[mt][1] = __float_as_uint(Al[(r + 8) * SMS + k0 + tig]);
            al[mt][2] = __float_as_uint(Al[r * SMS + k0 + tig + 4]);
            al[mt][3] = __float_as_uint(Al[(r + 8) * SMS + k0 + tig + 4]);
        }
#pragma unroll
        for (int nt = 0; nt < 8; nt++) {
            int nn = wc * 64 + nt * 8 + g;
            b[nt][0] = __float_as_uint(Bb[nn * SMS + k0 + tig]);
            b[nt][1] = __float_as_uint(Bb[nn * SMS + k0 + tig + 4]);
        }
#pragma unroll
        for (int mt = 0; mt < 2; mt++)
#pragma unroll
            for (int nt = 0; nt < 8; nt++) {
                MMA_TF32(acc[mt][nt], ah[mt], b[nt]);
                MMA_TF32(acc[mt][nt], al[mt], b[nt]);
            }
    }
    __syncthreads();
    for (int i = tx; i < 4096; i += 256)
        Bb4base[(i >> 5) * (SMS >> 2) + (i & 31)] = imgW2l[i];
    __syncthreads();

    // ---- pass 4: h1_hi * W2_lo ----
#pragma unroll
    for (int ks = 0; ks < 16; ks++) {
        int k0 = ks * 8;
        uint32_t ah[2][4], b[8][2];
#pragma unroll
        for (int mt = 0; mt < 2; mt++) {
            int r = wr * 32 + mt * 16 + g;
            ah[mt][0] = __float_as_uint(Ah[r * SMS + k0 + tig]);
            ah[mt][1] = __float_as_uint(Ah[(r + 8) * SMS + k0 + tig]);
            ah[mt][2] = __float_as_uint(Ah[r * SMS + k0 + tig + 4]);
            ah[mt][3] = __float_as_uint(Ah[(r + 8) * SMS + k0 + tig + 4]);
        }
#pragma unroll
        for (int nt = 0; nt < 8; nt++) {
            int nn = wc * 64 + nt * 8 + g;
            b[nt][0] = __float_as_uint(Bb[nn * SMS + k0 + tig]);
            b[nt][1] = __float_as_uint(Bb[nn * SMS + k0 + tig + 4]);
        }
#pragma unroll
        for (int mt = 0; mt < 2; mt++)
#pragma unroll
            for (int nt = 0; nt < 8; nt++)
                MMA_TF32(acc[mt][nt], ah[mt], b[nt]);
    }

    // epilogue: write h2
#pragma unroll
    for (int mt = 0; mt < 2; mt++) {
        int r = wr * 32 + mt * 16 + g;
#pragma unroll
        for (int nt = 0; nt < 8; nt++) {
            int c0 = wc * 64 + nt * 8 + 2 * tig;
            if (r < rowsValid)
                *(float2*)&out[(size_t)(row0 + r) * D + c0] =
                    make_float2(acc[mt][nt][0], acc[mt][nt][1]);
            if (r + 8 < rowsValid)
                *(float2*)&out[(size_t)(row0 + r + 8) * D + c0] =
                    make_float2(acc[mt][nt][2], acc[mt][nt][3]);
        }
    }
}

// ---------------- column stats over h2 (L2-hot) ----------------
__global__ void colstat_kernel(const float* __restrict__ h2, int layer, int n) {
    __shared__ float ss[256], sq[256];
    int tx = threadIdx.x;
    int col = tx & 127, half = tx >> 7;
    float s = 0.f, q = 0.f;
    int r0 = blockIdx.x * 256;
    int rend = min(r0 + 256, n);
    for (int r = r0 + half; r < rend; r += 2) {
        float v = h2[(size_t)r * D + col];
        s += v; q += v * v;
    }
    ss[tx] = s; sq[tx] = q;
    __syncthreads();
    if (tx < 128) {
        atomicAdd(&g_colsum[layer * D + tx],   ss[tx] + ss[tx + 128]);
        atomicAdd(&g_colsumsq[layer * D + tx], sq[tx] + sq[tx + 128]);
    }
}

// ---------------- finalize BN coefficients ----------------
__global__ void bnprep_kernel(int layer, const float* __restrict__ gamma,
                              const float* __restrict__ beta, float invN) {
    int c = threadIdx.x;
    float mu = g_colsum[layer * D + c] * invN;
    float var = g_colsumsq[layer * D + c] * invN - mu * mu;
    float inv = rsqrtf(var + BN_EPS);
    float sc = gamma[c] * inv;
    g_scale[c] = sc;
    g_shift[c] = beta[c] - mu * sc;
}

// ---------------- normalize (+relu) -> z_cat slice, atomic pool -> g_cat slice ----------------
__global__ void bnpool_kernel(const float* __restrict__ h2, const int* __restrict__ batch,
                              float* __restrict__ zout, float* __restrict__ gout,
                              int n, int do_relu) {
    int stride = gridDim.x * blockDim.x;
    for (int idx = blockIdx.x * blockDim.x + threadIdx.x; idx < n * 32; idx += stride) {
        int node = idx >> 5;
        int c = (idx & 31) * 4;
        float4 v = *(const float4*)&h2[(size_t)node * D + c];
        float4 sc = *(const float4*)&g_scale[c];
        float4 sh = *(const float4*)&g_shift[c];
        float y0 = v.x * sc.x + sh.x;
        float y1 = v.y * sc.y + sh.y;
        float y2 = v.z * sc.z + sh.z;
        float y3 = v.w * sc.w + sh.w;
        if (do_relu) {
            y0 = fmaxf(y0, 0.f); y1 = fmaxf(y1, 0.f);
            y2 = fmaxf(y2, 0.f); y3 = fmaxf(y3, 0.f);
        }
        float4 y4 = make_float4(y0, y1, y2, y3);
        *(float4*)&zout[(size_t)node * (3 * D) + c] = y4;
        int b = batch[node];
        float* gp = &gout[(size_t)b * (3 * D) + c];
        atomicAdd(gp + 0, y0);
        atomicAdd(gp + 1, y1);
        atomicAdd(gp + 2, y2);
        atomicAdd(gp + 3, y3);
    }
}

// ---------------- launch ----------------
extern "C" void kernel_launch(void* const* d_in, const int* in_sizes, int n_in,
                              void* d_out, int out_size) {
    const float* x     = (const float*)d_in[0];
    const int*   ei    = (const int*)d_in[1];
    const int*   batch = (const int*)d_in[2];
    const float* W1    = (const float*)d_in[3];
    const float* b1    = (const float*)d_in[4];
    const float* W2    = (const float*)d_in[5];
    const float* b2    = (const float*)d_in[6];
    const float* gamma = (const float*)d_in[7];
    const float* beta  = (const float*)d_in[8];

    int N = in_sizes[0] / D;
    int E = in_sizes[1] / 2;
    int G = out_size / (LAYERS * D) - N;

    float* out   = (float*)d_out;
    float* gpool = out + (size_t)N * LAYERS * D;
    int npool = G * LAYERS * D;

    const int* src = ei;
    const int* dst = ei + E;

    cudaFuncSetAttribute(mlp_kernel, cudaFuncAttributeMaxDynamicSharedMemorySize, MLP_SMEM);

    float* h0 = nullptr; float* h2 = nullptr; float* wimg = nullptr;
    cudaGetSymbolAddress((void**)&h0, g_h0);
    cudaGetSymbolAddress((void**)&h2, g_h2);
    cudaGetSymbolAddress((void**)&wimg, g_wimg);

    // zero scratch + pooled output; CSR build; weight image build
    zero_kernel<<<512, 256>>>(N, gpool, npool);
    int eb = (E + 255) / 256;
    hist_kernel<<<eb, 256>>>(dst, E);
    int chunk = (N + 1023) / 1024;
    scan_kernel<<<1, 1024>>>(N, chunk);
    scatter_kernel<<<eb, 256>>>(src, dst, E);
    wtrans_kernel<<<(12 * 16384 + 255) / 256, 256>>>(W1, W2);

    int aggBlocks = (N * 32 + 255) / 256;
    int mlpBlocks = (N + 127) / 128;
    int statBlocks = (N + 255) / 256;
    float invN = 1.0f / (float)N;

    for (int l = 0; l < LAYERS; l++) {
        const float* zbase;
        int zstride;
        if (l == 0) { zbase = x;                  zstride = D; }
        else        { zbase = out + (l - 1) * D;  zstride = 3 * D; }

        agg_kernel<<<aggBlocks, 256>>>(zbase, zstride, N);
        mlp_kernel<<<mlpBlocks, 256, MLP_SMEM>>>(h0, wimg + (size_t)l * 4 * 16384,
                                                 b1 + l * D, b2 + l * D, h2, N);
        colstat_kernel<<<statBlocks, 256>>>(h2, l, N);
        bnprep_kernel<<<1, D>>>(l, gamma + l * D, beta + l * D, invN);
        bnpool_kernel<<<aggBlocks, 256>>>(h2, batch, out + l * D,
                                          gpool + l * D, N, (l != LAYERS - 1) ? 1 : 0);
    }
}

// round 6
// speedup vs baseline: 1.3121x; 1.2215x over previous
#include <cuda_runtime.h>
#include <cstdint>

#define D 128
#define LAYERS 3
#define MAXN 50000
#define MAXE 1600000
#define BN_EPS 1e-5f
#define SMS 132   // smem row stride (floats)

// ---------------- scratch (static device globals; no allocation) ----------------
__device__ int   g_counts[MAXN];
__device__ int   g_ptr[MAXN + 1];
__device__ int   g_cursor[MAXN];
__device__ int   g_csr[MAXE];
__device__ float g_h0[(size_t)MAXN * D];     // agg + self
__device__ float g_h2[(size_t)MAXN * D];     // MLP output (pre-BN)
__device__ float g_wimg[12 * 16384];         // per layer: W1_hi, W1_lo, W2_hi, W2_lo (transposed [n][k])
__device__ float g_colsum[LAYERS * D];
__device__ float g_colsumsq[LAYERS * D];
__device__ float g_scale[D];
__device__ float g_shift[D];

__device__ __forceinline__ uint32_t to_tf32(float x) {
    uint32_t r; asm("cvt.rna.tf32.f32 %0, %1;" : "=r"(r) : "f"(x)); return r;
}

#define MMA_TF32(d, a, b) \
    asm volatile("mma.sync.aligned.m16n8k8.row.col.f32.tf32.tf32.f32 " \
        "{%0,%1,%2,%3}, {%4,%5,%6,%7}, {%8,%9}, {%0,%1,%2,%3};" \
        : "+f"((d)[0]), "+f"((d)[1]), "+f"((d)[2]), "+f"((d)[3]) \
        : "r"((a)[0]), "r"((a)[1]), "r"((a)[2]), "r"((a)[3]), \
          "r"((b)[0]), "r"((b)[1]))

// ---------------- zero scratch + pooled-output region ----------------
__global__ void zero_kernel(int n, float* gpool, int npool) {
    int stride = gridDim.x * blockDim.x;
    int t0 = blockIdx.x * blockDim.x + threadIdx.x;
    for (int i = t0; i < n; i += stride) g_counts[i] = 0;
    for (int i = t0; i < LAYERS * D; i += stride) { g_colsum[i] = 0.f; g_colsumsq[i] = 0.f; }
    for (int i = t0; i < npool; i += stride) gpool[i] = 0.f;
}

// ---------------- CSR build: histogram -> scan -> scatter ----------------
__global__ void hist_kernel(const int* __restrict__ dst, int e) {
    int i = blockIdx.x * blockDim.x + threadIdx.x;
    if (i < e) atomicAdd(&g_counts[dst[i]], 1);
}

__global__ void scan_kernel(int n, int chunk) {
    __shared__ int ssum[1024];
    int t = threadIdx.x;
    int lo = t * chunk;
    int hi = min(lo + chunk, n);
    int local = 0;
    for (int i = lo; i < hi; i++) local += g_counts[i];
    ssum[t] = local;
    __syncthreads();
    for (int off = 1; off < 1024; off <<= 1) {
        int v = 0;
        if (t >= off) v = ssum[t - off];
        __syncthreads();
        ssum[t] += v;
        __syncthreads();
    }
    int run = ssum[t] - local;
    for (int i = lo; i < hi; i++) {
        g_ptr[i] = run;
        g_cursor[i] = run;
        run += g_counts[i];
    }
    if (t == 1023) g_ptr[n] = ssum[1023];
}

__global__ void scatter_kernel(const int* __restrict__ src, const int* __restrict__ dst, int e) {
    int i = blockIdx.x * blockDim.x + threadIdx.x;
    if (i < e) {
        int p = atomicAdd(&g_cursor[dst[i]], 1);
        g_csr[p] = src[i];
    }
}

// ---------------- pre-transpose + hi/lo tf32 split of all weights ----------------
// image index w = l*4 + j, j: 0=W1_hi 1=W1_lo 2=W2_hi 3=W2_lo ; layout Wt[n][k]
__global__ void wtrans_kernel(const float* __restrict__ W1, const float* __restrict__ W2) {
    int i = blockIdx.x * blockDim.x + threadIdx.x;
    if (i >= 12 * 16384) return;
    int w = i >> 14, e = i & 16383;
    int l = w >> 2, j = w & 3;
    const float* src = (j < 2) ? W1 : W2;
    int nn = e >> 7, k = e & 127;
    float v = src[l * 16384 + k * 128 + nn];
    float hi = __uint_as_float(to_tf32(v));
    float outv = (j & 1) ? __uint_as_float(to_tf32(v - hi)) : hi;
    g_wimg[w * 16384 + nn * 128 + k] = outv;
}

// ---------------- per-node gather-sum (GIN agg + self), one warp per node ----------------
__global__ void agg_kernel(const float* __restrict__ zbase, int zstride, int n) {
    int warp = (blockIdx.x * blockDim.x + threadIdx.x) >> 5;
    int lane = threadIdx.x & 31;
    if (warp >= n) return;
    const float* zr = zbase + (size_t)warp * zstride + lane * 4;
    float4 a = *(const float4*)zr;   // self (eps = 0)
    int lo = g_ptr[warp], hi = g_ptr[warp + 1];
    for (int e = lo; e < hi; e++) {
        int s = g_csr[e];
        float4 v = __ldg((const float4*)(zbase + (size_t)s * zstride + lane * 4));
        a.x += v.x; a.y += v.y; a.z += v.z; a.w += v.w;
    }
    *(float4*)&g_h0[(size_t)warp * D + lane * 4] = a;
}

// ---------------- fused MLP via tf32x3 mma.sync: h2 = relu(h0@W1+b1)@W2+b2 ----------------
// smem: Ah[128*SMS] | Al[128*SMS] | Bb[128*SMS]  = 3*128*132*4 = 202752 bytes
#define MLP_SMEM (3 * 128 * SMS * 4)

__global__ void __launch_bounds__(512, 1)
mlp_kernel(const float* __restrict__ A, const float* __restrict__ img,
           const float* __restrict__ b1, const float* __restrict__ b2,
           float* __restrict__ out, int n)
{
    extern __shared__ float sm[];
    float* Ah = sm;
    float* Al = Ah + 128 * SMS;
    float* Bb = Al + 128 * SMS;
    int tx = threadIdx.x;
    int wid = tx >> 5, lane = tx & 31;
    int g = lane >> 2, tig = lane & 3;
    int wr = wid & 3, wc = wid >> 2;       // 4 row-warps x 4 col-warps
    int row0 = blockIdx.x * 128;
    int rowsValid = min(128, n - row0);

    const float4* imgW1h = (const float4*)(img);
    const float4* imgW1l = (const float4*)(img + 16384);
    const float4* imgW2h = (const float4*)(img + 2 * 16384);
    const float4* imgW2l = (const float4*)(img + 3 * 16384);
    float4* Bb4base = (float4*)Bb;

    // stage A hi/lo + W1_hi
    for (int i = tx; i < 4096; i += 512) {
        int r = i >> 5, c4 = (i & 31) * 4;
        float4 v = make_float4(0.f, 0.f, 0.f, 0.f);
        if (r < rowsValid) v = *(const float4*)&A[(size_t)(row0 + r) * D + c4];
        float4 h;
        h.x = __uint_as_float(to_tf32(v.x));
        h.y = __uint_as_float(to_tf32(v.y));
        h.z = __uint_as_float(to_tf32(v.z));
        h.w = __uint_as_float(to_tf32(v.w));
        float4 l;
        l.x = __uint_as_float(to_tf32(v.x - h.x));
        l.y = __uint_as_float(to_tf32(v.y - h.y));
        l.z = __uint_as_float(to_tf32(v.z - h.z));
        l.w = __uint_as_float(to_tf32(v.w - h.w));
        *(float4*)&Ah[r * SMS + c4] = h;
        *(float4*)&Al[r * SMS + c4] = l;
        Bb4base[(i >> 5) * (SMS >> 2) + (i & 31)] = imgW1h[i];
    }
    __syncthreads();

    float acc[2][4][4];

    // ---- acc = b1 ----
#pragma unroll
    for (int nt = 0; nt < 4; nt++) {
        int c0 = wc * 32 + nt * 8 + 2 * tig;
        float bx = __ldg(&b1[c0]), by = __ldg(&b1[c0 + 1]);
#pragma unroll
        for (int mt = 0; mt < 2; mt++) {
            acc[mt][nt][0] = bx; acc[mt][nt][1] = by;
            acc[mt][nt][2] = bx; acc[mt][nt][3] = by;
        }
    }

    // ---- pass 1: (A_hi + A_lo) * W1_hi ----
#pragma unroll
    for (int ks = 0; ks < 16; ks++) {
        int k0 = ks * 8;
        uint32_t ah[2][4], al[2][4], b[4][2];
#pragma unroll
        for (int mt = 0; mt < 2; mt++) {
            int r = wr * 32 + mt * 16 + g;
            ah[mt][0] = __float_as_uint(Ah[r * SMS + k0 + tig]);
            ah[mt][1] = __float_as_uint(Ah[(r + 8) * SMS + k0 + tig]);
            ah[mt][2] = __float_as_uint(Ah[r * SMS + k0 + tig + 4]);
            ah[mt][3] = __float_as_uint(Ah[(r + 8) * SMS + k0 + tig + 4]);
            al[mt][0] = __float_as_uint(Al[r * SMS + k0 + tig]);
            al[mt][1] = __float_as_uint(Al[(r + 8) * SMS + k0 + tig]);
            al[mt][2] = __float_as_uint(Al[r * SMS + k0 + tig + 4]);
            al[mt][3] = __float_as_uint(Al[(r + 8) * SMS + k0 + tig + 4]);
        }
#pragma unroll
        for (int nt = 0; nt < 4; nt++) {
            int nn = wc * 32 + nt * 8 + g;
            b[nt][0] = __float_as_uint(Bb[nn * SMS + k0 + tig]);
            b[nt][1] = __float_as_uint(Bb[nn * SMS + k0 + tig + 4]);
        }
#pragma unroll
        for (int mt = 0; mt < 2; mt++)
#pragma unroll
            for (int nt = 0; nt < 4; nt++) {
                MMA_TF32(acc[mt][nt], ah[mt], b[nt]);
                MMA_TF32(acc[mt][nt], al[mt], b[nt]);
            }
    }
    __syncthreads();
    for (int i = tx; i < 4096; i += 512)
        Bb4base[(i >> 5) * (SMS >> 2) + (i & 31)] = imgW1l[i];
    __syncthreads();

    // ---- pass 2: A_hi * W1_lo ----
#pragma unroll
    for (int ks = 0; ks < 16; ks++) {
        int k0 = ks * 8;
        uint32_t ah[2][4], b[4][2];
#pragma unroll
        for (int mt = 0; mt < 2; mt++) {
            int r = wr * 32 + mt * 16 + g;
            ah[mt][0] = __float_as_uint(Ah[r * SMS + k0 + tig]);
            ah[mt][1] = __float_as_uint(Ah[(r + 8) * SMS + k0 + tig]);
            ah[mt][2] = __float_as_uint(Ah[r * SMS + k0 + tig + 4]);
            ah[mt][3] = __float_as_uint(Ah[(r + 8) * SMS + k0 + tig + 4]);
        }
#pragma unroll
        for (int nt = 0; nt < 4; nt++) {
            int nn = wc * 32 + nt * 8 + g;
            b[nt][0] = __float_as_uint(Bb[nn * SMS + k0 + tig]);
            b[nt][1] = __float_as_uint(Bb[nn * SMS + k0 + tig + 4]);
        }
#pragma unroll
        for (int mt = 0; mt < 2; mt++)
#pragma unroll
            for (int nt = 0; nt < 4; nt++)
                MMA_TF32(acc[mt][nt], ah[mt], b[nt]);
    }
    __syncthreads();   // all warps done reading Ah/Al/Bb

    // relu(h1), hi/lo split back into Ah/Al; stage W2_hi into Bb
#pragma unroll
    for (int mt = 0; mt < 2; mt++) {
        int r = wr * 32 + mt * 16 + g;
#pragma unroll
        for (int nt = 0; nt < 4; nt++) {
            int c0 = wc * 32 + nt * 8 + 2 * tig;
#pragma unroll
            for (int q = 0; q < 4; q++) {
                int rr = (q < 2) ? r : r + 8;
                int cc = c0 + (q & 1);
                float v = fmaxf(acc[mt][nt][q], 0.f);
                float h = __uint_as_float(to_tf32(v));
                Ah[rr * SMS + cc] = h;
                Al[rr * SMS + cc] = __uint_as_float(to_tf32(v - h));
            }
        }
    }
    for (int i = tx; i < 4096; i += 512)
        Bb4base[(i >> 5) * (SMS >> 2) + (i & 31)] = imgW2h[i];
    __syncthreads();

    // ---- acc = b2 ----
#pragma unroll
    for (int nt = 0; nt < 4; nt++) {
        int c0 = wc * 32 + nt * 8 + 2 * tig;
        float bx = __ldg(&b2[c0]), by = __ldg(&b2[c0 + 1]);
#pragma unroll
        for (int mt = 0; mt < 2; mt++) {
            acc[mt][nt][0] = bx; acc[mt][nt][1] = by;
            acc[mt][nt][2] = bx; acc[mt][nt][3] = by;
        }
    }

    // ---- pass 3: (h1_hi + h1_lo) * W2_hi ----
#pragma unroll
    for (int ks = 0; ks < 16; ks++) {
        int k0 = ks * 8;
        uint32_t ah[2][4], al[2][4], b[4][2];
#pragma unroll
        for (int mt = 0; mt < 2; mt++) {
            int r = wr * 32 + mt * 16 + g;
            ah[mt][0] = __float_as_uint(Ah[r * SMS + k0 + tig]);
            ah[mt][1] = __float_as_uint(Ah[(r + 8) * SMS + k0 + tig]);
            ah[mt][2] = __float_as_uint(Ah[r * SMS + k0 + tig + 4]);
            ah[mt][3] = __float_as_uint(Ah[(r + 8) * SMS + k0 + tig + 4]);
            al[mt][0] = __float_as_uint(Al[r * SMS + k0 + tig]);
            al[mt][1] = __float_as_uint(Al[(r + 8) * SMS + k0 + tig]);
            al[mt][2] = __float_as_uint(Al[r * SMS + k0 + tig + 4]);
            al[mt][3] = __float_as_uint(Al[(r + 8) * SMS + k0 + tig + 4]);
        }
#pragma unroll
        for (int nt = 0; nt < 4; nt++) {
            int nn = wc * 32 + nt * 8 + g;
            b[nt][0] = __float_as_uint(Bb[nn * SMS + k0 + tig]);
            b[nt][1] = __float_as_uint(Bb[nn * SMS + k0 + tig + 4]);
        }
#pragma unroll
        for (int mt = 0; mt < 2; mt++)
#pragma unroll
            for (int nt = 0; nt < 4; nt++) {
                MMA_TF32(acc[mt][nt], ah[mt], b[nt]);
                MMA_TF32(acc[mt][nt], al[mt], b[nt]);
            }
    }
    __syncthreads();
    for (int i = tx; i < 4096; i += 512)
        Bb4base[(i >> 5) * (SMS >> 2) + (i & 31)] = imgW2l[i];
    __syncthreads();

    // ---- pass 4: h1_hi * W2_lo ----
#pragma unroll
    for (int ks = 0; ks < 16; ks++) {
        int k0 = ks * 8;
        uint32_t ah[2][4], b[4][2];
#pragma unroll
        for (int mt = 0; mt < 2; mt++) {
            int r = wr * 32 + mt * 16 + g;
            ah[mt][0] = __float_as_uint(Ah[r * SMS + k0 + tig]);
            ah[mt][1] = __float_as_uint(Ah[(r + 8) * SMS + k0 + tig]);
            ah[mt][2] = __float_as_uint(Ah[r * SMS + k0 + tig + 4]);
            ah[mt][3] = __float_as_uint(Ah[(r + 8) * SMS + k0 + tig + 4]);
        }
#pragma unroll
        for (int nt = 0; nt < 4; nt++) {
            int nn = wc * 32 + nt * 8 + g;
            b[nt][0] = __float_as_uint(Bb[nn * SMS + k0 + tig]);
            b[nt][1] = __float_as_uint(Bb[nn * SMS + k0 + tig + 4]);
        }
#pragma unroll
        for (int mt = 0; mt < 2; mt++)
#pragma unroll
            for (int nt = 0; nt < 4; nt++)
                MMA_TF32(acc[mt][nt], ah[mt], b[nt]);
    }

    // epilogue: write h2
#pragma unroll
    for (int mt = 0; mt < 2; mt++) {
        int r = wr * 32 + mt * 16 + g;
#pragma unroll
        for (int nt = 0; nt < 4; nt++) {
            int c0 = wc * 32 + nt * 8 + 2 * tig;
            if (r < rowsValid)
                *(float2*)&out[(size_t)(row0 + r) * D + c0] =
                    make_float2(acc[mt][nt][0], acc[mt][nt][1]);
            if (r + 8 < rowsValid)
                *(float2*)&out[(size_t)(row0 + r + 8) * D + c0] =
                    make_float2(acc[mt][nt][2], acc[mt][nt][3]);
        }
    }
}

// ---------------- column stats over h2 (L2-hot) ----------------
__global__ void colstat_kernel(const float* __restrict__ h2, int layer, int n) {
    __shared__ float ss[256], sq[256];
    int tx = threadIdx.x;
    int col = tx & 127, half = tx >> 7;
    float s = 0.f, q = 0.f;
    int r0 = blockIdx.x * 256;
    int rend = min(r0 + 256, n);
    for (int r = r0 + half; r < rend; r += 2) {
        float v = h2[(size_t)r * D + col];
        s += v; q += v * v;
    }
    ss[tx] = s; sq[tx] = q;
    __syncthreads();
    if (tx < 128) {
        atomicAdd(&g_colsum[layer * D + tx],   ss[tx] + ss[tx + 128]);
        atomicAdd(&g_colsumsq[layer * D + tx], sq[tx] + sq[tx + 128]);
    }
}

// ---------------- finalize BN coefficients ----------------
__global__ void bnprep_kernel(int layer, const float* __restrict__ gamma,
                              const float* __restrict__ beta, float invN) {
    int c = threadIdx.x;
    float mu = g_colsum[layer * D + c] * invN;
    float var = g_colsumsq[layer * D + c] * invN - mu * mu;
    float inv = rsqrtf(var + BN_EPS);
    float sc = gamma[c] * inv;
    g_scale[c] = sc;
    g_shift[c] = beta[c] - mu * sc;
}

// ---------------- normalize (+relu) -> z_cat slice, segmented pool -> g_cat slice ----------------
// batch is sorted, so along each thread's strided row subsequence the graph id is
// nondecreasing: keep a running sum, flush with one atomicAdd at run boundaries.
#define POOL_ROWS 256
__global__ void __launch_bounds__(512, 2)
bnpool_kernel(const float* __restrict__ h2, const int* __restrict__ batch,
              float* __restrict__ zout, float* __restrict__ gout,
              int n, int do_relu) {
    __shared__ int sb[POOL_ROWS];
    int tx = threadIdx.x;
    int c = tx & 127, sub = tx >> 7;   // 4 row phases
    int r0 = blockIdx.x * POOL_ROWS;
    int rcount = min(POOL_ROWS, n - r0);
    for (int i = tx; i < rcount; i += 512) sb[i] = batch[r0 + i];
    __syncthreads();
    float sc = g_scale[c], sh = g_shift[c];
    float run = 0.f;
    int cur = -1;
    for (int i = sub; i < rcount; i += 4) {
        int r = r0 + i;
        float y = h2[(size_t)r * D + c] * sc + sh;
        if (do_relu) y = fmaxf(y, 0.f);
        zout[(size_t)r * (3 * D) + c] = y;
        int b = sb[i];
        if (b != cur) {
            if (cur >= 0) atomicAdd(&gout[(size_t)cur * (3 * D) + c], run);
            run = 0.f; cur = b;
        }
        run += y;
    }
    if (cur >= 0) atomicAdd(&gout[(size_t)cur * (3 * D) + c], run);
}

// ---------------- launch ----------------
extern "C" void kernel_launch(void* const* d_in, const int* in_sizes, int n_in,
                              void* d_out, int out_size) {
    const float* x     = (const float*)d_in[0];
    const int*   ei    = (const int*)d_in[1];
    const int*   batch = (const int*)d_in[2];
    const float* W1    = (const float*)d_in[3];
    const float* b1    = (const float*)d_in[4];
    const float* W2    = (const float*)d_in[5];
    const float* b2    = (const float*)d_in[6];
    const float* gamma = (const float*)d_in[7];
    const float* beta  = (const float*)d_in[8];

    int N = in_sizes[0] / D;
    int E = in_sizes[1] / 2;
    int G = out_size / (LAYERS * D) - N;

    float* out   = (float*)d_out;
    float* gpool = out + (size_t)N * LAYERS * D;
    int npool = G * LAYERS * D;

    const int* src = ei;
    const int* dst = ei + E;

    cudaFuncSetAttribute(mlp_kernel, cudaFuncAttributeMaxDynamicSharedMemorySize, MLP_SMEM);

    float* h0 = nullptr; float* h2 = nullptr; float* wimg = nullptr;
    cudaGetSymbolAddress((void**)&h0, g_h0);
    cudaGetSymbolAddress((void**)&h2, g_h2);
    cudaGetSymbolAddress((void**)&wimg, g_wimg);

    // zero scratch + pooled output; CSR build; weight image build
    zero_kernel<<<512, 256>>>(N, gpool, npool);
    int eb = (E + 255) / 256;
    hist_kernel<<<eb, 256>>>(dst, E);
    int chunk = (N + 1023) / 1024;
    scan_kernel<<<1, 1024>>>(N, chunk);
    scatter_kernel<<<eb, 256>>>(src, dst, E);
    wtrans_kernel<<<(12 * 16384 + 255) / 256, 256>>>(W1, W2);

    int aggBlocks = (N * 32 + 255) / 256;
    int mlpBlocks = (N + 127) / 128;
    int statBlocks = (N + 255) / 256;
    int poolBlocks = (N + POOL_ROWS - 1) / POOL_ROWS;
    float invN = 1.0f / (float)N;

    for (int l = 0; l < LAYERS; l++) {
        const float* zbase;
        int zstride;
        if (l == 0) { zbase = x;                  zstride = D; }
        else        { zbase = out + (l - 1) * D;  zstride = 3 * D; }

        agg_kernel<<<aggBlocks, 256>>>(zbase, zstride, N);
        mlp_kernel<<<mlpBlocks, 512, MLP_SMEM>>>(h0, wimg + (size_t)l * 4 * 16384,
                                                 b1 + l * D, b2 + l * D, h2, N);
        colstat_kernel<<<statBlocks, 256>>>(h2, l, N);
        bnprep_kernel<<<1, D>>>(l, gamma + l * D, beta + l * D, invN);
        bnpool_kernel<<<poolBlocks, 512>>>(h2, batch, out + l * D,
                                           gpool + l * D, N, (l != LAYERS - 1) ? 1 : 0);
    }
}